// round 3
// baseline (speedup 1.0000x reference)
#include <cuda_runtime.h>
#include <cstdint>
#include <math.h>

#define HEADS   8
#define DHQK    32
#define DHV     32
#define BSZ     8
#define HALO    3
#define WIN     14
#define WIN2    196
#define NPAD    224
#define QKVW    768
#define NPIX    4096
#define NBATCH  16
#define SCALE_QK 0.17677669529663687f

// Scratch: fused qkv per pixel, layout [b][pix][768]:
//   [0,256)   q  : channel = head*32 + d
//   [256,768) kv : channel = head*64 + d (k: d<32, v: d>=32)
__device__ float g_qkv[(size_t)NBATCH * NPIX * QKVW];

__device__ __forceinline__ uint32_t f2tf(float f) {   // round-to-nearest tf32
    uint32_t r;
    asm("cvt.rna.tf32.f32 %0, %1;" : "=r"(r) : "f"(f));
    return r;
}

__device__ __forceinline__ void mma_tf32(float c[4], const uint32_t a[4],
                                         const uint32_t b[2]) {
    asm volatile(
        "mma.sync.aligned.m16n8k8.row.col.f32.tf32.tf32.f32 "
        "{%0,%1,%2,%3}, {%4,%5,%6,%7}, {%8,%9}, {%0,%1,%2,%3};"
        : "+f"(c[0]), "+f"(c[1]), "+f"(c[2]), "+f"(c[3])
        : "r"(a[0]), "r"(a[1]), "r"(a[2]), "r"(a[3]), "r"(b[0]), "r"(b[1]));
}

// =====================================================================
// Kernel 1: fused QKV projection GEMM on mma.sync tf32 (m16n8k8)
//   D[128 pix][128 ch] = A[128 pix][256 c] * W[128 ch][256 c]^T
//   Block 128x128, 8 warps (2M x 4N), warp tile 64x32.
//   Double-buffered smem, K-chunk 32, layout [row][k] stride 36
//   (conflict-free fragment LDS and staging STS).
// =====================================================================
#define KST 36                       // smem row stride in floats
#define BUF_FLOATS (128 * KST)       // 4608 floats per operand tile
#define GE_SMEM_BYTES (2 * 2 * BUF_FLOATS * 4)   // 73728

__global__ __launch_bounds__(256) void qkv_gemm_mma(const float* __restrict__ x,
                                                    const float* __restrict__ Wq,
                                                    const float* __restrict__ Wkv) {
    extern __shared__ float sm[];   // buf b: A at b*9216, B at b*9216+4608

    const int tid = threadIdx.x, wid = tid >> 5, lane = tid & 31;
    const int wm = wid >> 2;        // 0..1  (64 M rows each)
    const int wn = wid & 3;         // 0..3  (32 N cols each)
    const int g = lane >> 2, t = lane & 3;

    const int n0   = blockIdx.x * 128;     // 0..640, never straddles q/kv split
    const int mblk = blockIdx.y;           // 0..511
    const int b    = mblk >> 5;
    const int pix0 = (mblk & 31) << 7;
    const float* xb = x + (size_t)b * 256 * NPIX + pix0;
    const float* Wb = (n0 < 256) ? (Wq + (size_t)n0 * 256)
                                 : (Wkv + (size_t)(n0 - 256) * 256);

    float acc[4][4][4];
    #pragma unroll
    for (int mt = 0; mt < 4; ++mt)
        #pragma unroll
        for (int nt = 0; nt < 4; ++nt)
            #pragma unroll
            for (int i = 0; i < 4; ++i) acc[mt][nt][i] = 0.f;

    // staging index precompute
    const int am  = tid & 127;      // pixel row within tile
    const int akb = tid >> 7;       // 0/1: kg = akb + 2p
    const int bn  = tid >> 1;       // W row 0..127
    const int bh  = tid & 1;        // which 16-float half of the 32-k chunk

    // ---- prologue: stage chunk 0 into buffer 0 ----
    {
        float* A0 = sm;
        float* B0 = sm + BUF_FLOATS;
        #pragma unroll
        for (int p = 0; p < 4; ++p) {
            const int kg = akb + 2 * p;
            const float* xs = xb + (size_t)(kg * 4) * NPIX + am;
            float* dst = A0 + am * KST + kg * 4;
            #pragma unroll
            for (int j = 0; j < 4; ++j)
                dst[j] = __uint_as_float(f2tf(xs[(size_t)j * NPIX]));
        }
        const float* wp = Wb + (size_t)bn * 256 + bh * 16;
        float* bd = B0 + bn * KST + bh * 16;
        #pragma unroll
        for (int j = 0; j < 4; ++j) {
            float4 v = *(const float4*)(wp + 4 * j);
            float4 tv = make_float4(__uint_as_float(f2tf(v.x)), __uint_as_float(f2tf(v.y)),
                                    __uint_as_float(f2tf(v.z)), __uint_as_float(f2tf(v.w)));
            *(float4*)(bd + 4 * j) = tv;
        }
    }
    __syncthreads();

    const int mrow_s = wm * 64 + g;      // smem row base for A fragments
    const int nrow_s = wn * 32 + g;      // smem row base for B fragments

    for (int c = 0; c < 8; ++c) {
        const int cur = c & 1, nxt = cur ^ 1;

        // ---- issue global loads for chunk c+1 into registers ----
        float a_reg[4][4];
        float4 b_reg[4];
        if (c < 7) {
            const int kc = (c + 1) * 32;
            #pragma unroll
            for (int p = 0; p < 4; ++p) {
                const int kg = akb + 2 * p;
                const float* xs = xb + (size_t)(kc + kg * 4) * NPIX + am;
                #pragma unroll
                for (int j = 0; j < 4; ++j) a_reg[p][j] = xs[(size_t)j * NPIX];
            }
            const float* wp = Wb + (size_t)bn * 256 + kc + bh * 16;
            #pragma unroll
            for (int j = 0; j < 4; ++j) b_reg[j] = *(const float4*)(wp + 4 * j);
        }

        // ---- compute chunk c from buffer cur ----
        const float* A = sm + cur * 2 * BUF_FLOATS;
        const float* B = A + BUF_FLOATS;
        #pragma unroll
        for (int ks = 0; ks < 4; ++ks) {
            const int kb = ks * 8;
            uint32_t af[4][4], bf[4][2];
            #pragma unroll
            for (int mt = 0; mt < 4; ++mt) {
                const float* ap = A + (mrow_s + mt * 16) * KST + kb + t;
                af[mt][0] = __float_as_uint(ap[0]);
                af[mt][1] = __float_as_uint(ap[8 * KST]);
                af[mt][2] = __float_as_uint(ap[4]);
                af[mt][3] = __float_as_uint(ap[8 * KST + 4]);
            }
            #pragma unroll
            for (int nt = 0; nt < 4; ++nt) {
                const float* bp = B + (nrow_s + nt * 8) * KST + kb + t;
                bf[nt][0] = __float_as_uint(bp[0]);
                bf[nt][1] = __float_as_uint(bp[4]);
            }
            #pragma unroll
            for (int mt = 0; mt < 4; ++mt)
                #pragma unroll
                for (int nt = 0; nt < 4; ++nt)
                    mma_tf32(acc[mt][nt], af[mt], bf[nt]);
        }

        // ---- convert + store staged registers into buffer nxt ----
        if (c < 7) {
            float* An = sm + nxt * 2 * BUF_FLOATS;
            float* Bn = An + BUF_FLOATS;
            #pragma unroll
            for (int p = 0; p < 4; ++p) {
                const int kg = akb + 2 * p;
                float* dst = An + am * KST + kg * 4;
                float4 tv = make_float4(__uint_as_float(f2tf(a_reg[p][0])),
                                        __uint_as_float(f2tf(a_reg[p][1])),
                                        __uint_as_float(f2tf(a_reg[p][2])),
                                        __uint_as_float(f2tf(a_reg[p][3])));
                *(float4*)dst = tv;
            }
            float* bd = Bn + bn * KST + bh * 16;
            #pragma unroll
            for (int j = 0; j < 4; ++j) {
                float4 v = b_reg[j];
                float4 tv = make_float4(__uint_as_float(f2tf(v.x)), __uint_as_float(f2tf(v.y)),
                                        __uint_as_float(f2tf(v.z)), __uint_as_float(f2tf(v.w)));
                *(float4*)(bd + 4 * j) = tv;
            }
        }
        __syncthreads();
    }

    // ---- epilogue: float2 stores, 4 lanes cover a full 32B sector ----
    const size_t mrow0 = (size_t)b * NPIX + pix0;
    #pragma unroll
    for (int mt = 0; mt < 4; ++mt) {
        #pragma unroll
        for (int nt = 0; nt < 4; ++nt) {
            float* o = g_qkv + (mrow0 + wm * 64 + mt * 16 + g) * QKVW
                             + n0 + wn * 32 + nt * 8 + 2 * t;
            *(float2*)o = make_float2(acc[mt][nt][0], acc[mt][nt][1]);
            *(float2*)(o + (size_t)8 * QKVW) = make_float2(acc[mt][nt][2], acc[mt][nt][3]);
        }
    }
}

// =====================================================================
// Kernel 2: halo block attention (unchanged from R1 — 652us, fp32 SIMT)
// =====================================================================
__global__ __launch_bounds__(256) void attn_kernel(const float* __restrict__ pos_bias,
                                                   float* __restrict__ out) {
    extern __shared__ float sm[];
    float* Qs = sm;                       // [64][32]          2048 f
    float* Kt = sm + 2048;                // [32][225] (K->V)  7200 f
    float* Ps = sm + 2048 + 7200;         // [64][224]        14336 f

    const int nb = blockIdx.x, h = blockIdx.y, b = blockIdx.z;
    const int by = nb >> 3, bx = nb & 7;
    const int tid = threadIdx.x;
    const int w = tid >> 5, lane = tid & 31;
    const float* qkv_b = g_qkv + (size_t)b * NPIX * QKVW;

    #pragma unroll
    for (int it = 0; it < 2; ++it) {
        int idx = tid + it * 256;
        int r = idx >> 3, d4 = (idx & 7) << 2;
        int py = by * BSZ + (r >> 3), px = bx * BSZ + (r & 7);
        *(float4*)(Qs + r * 32 + d4) =
            *(const float4*)(qkv_b + (py * 64 + px) * QKVW + h * DHQK + d4);
    }
    for (int idx = tid; idx < WIN2 * 32; idx += 256) {
        int kk = idx >> 5, d = idx & 31;
        int wy = kk / WIN, wx = kk - wy * WIN;
        int py = by * BSZ - HALO + wy, px = bx * BSZ - HALO + wx;
        float v = 0.f;
        if ((unsigned)py < 64u && (unsigned)px < 64u)
            v = qkv_b[(py * 64 + px) * QKVW + 256 + h * 64 + d];
        Kt[d * 225 + kk] = v;
    }
    __syncthreads();

    float s[8][7];
    #pragma unroll
    for (int mi = 0; mi < 8; ++mi)
        #pragma unroll
        for (int nc = 0; nc < 7; ++nc) s[mi][nc] = 0.f;

    const float* qrow = Qs + (w * 8) * 32;
    #pragma unroll 4
    for (int d = 0; d < 32; ++d) {
        float kv[7];
        #pragma unroll
        for (int nc = 0; nc < 7; ++nc) kv[nc] = Kt[d * 225 + nc * 32 + lane];
        #pragma unroll
        for (int mi = 0; mi < 8; ++mi) {
            float qd = qrow[mi * 32 + d];
            #pragma unroll
            for (int nc = 0; nc < 7; ++nc) s[mi][nc] = fmaf(qd, kv[nc], s[mi][nc]);
        }
    }

    const float* pb = pos_bias + (size_t)(h * 64 + w * 8) * WIN2;
    const float NEG = -1e30f;
    #pragma unroll
    for (int mi = 0; mi < 8; ++mi) {
        #pragma unroll
        for (int nc = 0; nc < 7; ++nc) {
            int kk = nc * 32 + lane;
            s[mi][nc] = (kk < WIN2) ? fmaf(s[mi][nc], SCALE_QK, pb[mi * WIN2 + kk]) : NEG;
        }
        float mx = s[mi][0];
        #pragma unroll
        for (int nc = 1; nc < 7; ++nc) mx = fmaxf(mx, s[mi][nc]);
        #pragma unroll
        for (int off = 16; off > 0; off >>= 1)
            mx = fmaxf(mx, __shfl_xor_sync(0xffffffffu, mx, off));
        float sum = 0.f;
        #pragma unroll
        for (int nc = 0; nc < 7; ++nc) {
            float e = __expf(s[mi][nc] - mx);
            s[mi][nc] = e;
            sum += e;
        }
        #pragma unroll
        for (int off = 16; off > 0; off >>= 1)
            sum += __shfl_xor_sync(0xffffffffu, sum, off);
        float inv = 1.f / sum;
        #pragma unroll
        for (int nc = 0; nc < 7; ++nc)
            Ps[(w * 8 + mi) * NPAD + nc * 32 + lane] = s[mi][nc] * inv;
    }
    __syncthreads();

    for (int idx = tid; idx < WIN2 * 32; idx += 256) {
        int kk = idx >> 5, d = idx & 31;
        int wy = kk / WIN, wx = kk - wy * WIN;
        int py = by * BSZ - HALO + wy, px = bx * BSZ - HALO + wx;
        float v = 0.f;
        if ((unsigned)py < 64u && (unsigned)px < 64u)
            v = qkv_b[(py * 64 + px) * QKVW + 256 + h * 64 + 32 + d];
        Kt[d * 225 + kk] = v;
    }
    __syncthreads();

    float acc[8];
    #pragma unroll
    for (int mi = 0; mi < 8; ++mi) acc[mi] = 0.f;
    const float* vrow = Kt + lane * 225;
    const float* prow = Ps + (w * 8) * NPAD;
    for (int n4 = 0; n4 < WIN2 / 4; ++n4) {
        float v0 = vrow[n4 * 4 + 0];
        float v1 = vrow[n4 * 4 + 1];
        float v2 = vrow[n4 * 4 + 2];
        float v3 = vrow[n4 * 4 + 3];
        #pragma unroll
        for (int mi = 0; mi < 8; ++mi) {
            float4 p = *(const float4*)(prow + mi * NPAD + n4 * 4);
            acc[mi] = fmaf(p.x, v0, acc[mi]);
            acc[mi] = fmaf(p.y, v1, acc[mi]);
            acc[mi] = fmaf(p.z, v2, acc[mi]);
            acc[mi] = fmaf(p.w, v3, acc[mi]);
        }
    }

    #pragma unroll
    for (int mi = 0; mi < 8; ++mi)
        Qs[(w * 8 + mi) * 32 + lane] = acc[mi];
    __syncthreads();

    const int d = tid >> 3, qy = tid & 7;
    float v0 = Qs[(qy * 8 + 0) * 32 + d], v1 = Qs[(qy * 8 + 1) * 32 + d];
    float v2 = Qs[(qy * 8 + 2) * 32 + d], v3 = Qs[(qy * 8 + 3) * 32 + d];
    float v4 = Qs[(qy * 8 + 4) * 32 + d], v5 = Qs[(qy * 8 + 5) * 32 + d];
    float v6 = Qs[(qy * 8 + 6) * 32 + d], v7 = Qs[(qy * 8 + 7) * 32 + d];
    float* op = out + ((size_t)((b * HEADS + h) * DHV + d) * 64 + by * BSZ + qy) * 64
                    + bx * BSZ;
    *(float4*)(op)     = make_float4(v0, v1, v2, v3);
    *(float4*)(op + 4) = make_float4(v4, v5, v6, v7);
}

// =====================================================================
extern "C" void kernel_launch(void* const* d_in, const int* in_sizes, int n_in,
                              void* d_out, int out_size) {
    const float* x   = (const float*)d_in[0];
    const float* Wq  = (const float*)d_in[1];
    const float* Wkv = (const float*)d_in[2];
    const float* pb  = (const float*)d_in[3];
    float* out = (float*)d_out;

    // 1) tf32 mma.sync projection GEMM
    cudaFuncSetAttribute(qkv_gemm_mma,
                         cudaFuncAttributeMaxDynamicSharedMemorySize, GE_SMEM_BYTES);
    qkv_gemm_mma<<<dim3(6, 512), 256, GE_SMEM_BYTES>>>(x, Wq, Wkv);

    // 2) halo attention (unchanged)
    const int smem_bytes = (2048 + 7200 + 64 * NPAD) * 4;
    cudaFuncSetAttribute(attn_kernel,
                         cudaFuncAttributeMaxDynamicSharedMemorySize, smem_bytes);
    attn_kernel<<<dim3(64, HEADS, NBATCH), 256, smem_bytes>>>(pb, out);
}

// round 4
// speedup vs baseline: 1.1894x; 1.1894x over previous
#include <cuda_runtime.h>
#include <cstdint>
#include <math.h>

typedef unsigned long long ull;

#define HEADS   8
#define DHQK    32
#define DHV     32
#define BSZ     8
#define HALO    3
#define WIN     14
#define WIN2    196
#define QKVW    768
#define NPIX    4096
#define NBATCH  16
#define SCALE_QK 0.17677669529663687f

// Scratch: fused qkv per pixel, layout [b][pix][768]:
//   [0,256)   q  : channel = head*32 + d
//   [256,768) kv : channel = head*64 + d (k: d<32, v: d>=32)
__device__ float g_qkv[(size_t)NBATCH * NPIX * QKVW];

// ---------- packed f32x2 helpers ----------
__device__ __forceinline__ ull pk2(float lo, float hi) {
    ull r; asm("mov.b64 %0, {%1, %2};" : "=l"(r) : "f"(lo), "f"(hi)); return r;
}
__device__ __forceinline__ ull fma2(ull a, ull b, ull c) {
    ull d; asm("fma.rn.f32x2 %0, %1, %2, %3;" : "=l"(d) : "l"(a), "l"(b), "l"(c)); return d;
}
__device__ __forceinline__ float2 upk2(ull v) {
    float2 r; asm("mov.b64 {%0, %1}, %2;" : "=f"(r.x), "=f"(r.y) : "l"(v)); return r;
}

// =====================================================================
// Kernel 1: fused QKV projection GEMM (R1 version, f32x2, 575us)
// =====================================================================
__global__ __launch_bounds__(256) void qkv_gemm(const float* __restrict__ x,
                                                const float* __restrict__ Wq,
                                                const float* __restrict__ Wkv) {
    __shared__ float As[16 * 128];   // [kk][m]
    __shared__ float Bs[16 * 132];   // [kk][n], padded row stride 132

    const int n0   = blockIdx.x * 128;
    const int mblk = blockIdx.y;
    const int b    = mblk >> 5;
    const int pix0 = (mblk & 31) << 7;

    const float* xb = x + ((size_t)b * 256) * NPIX + pix0;
    const float* Wb = (n0 < 256) ? (Wq + (size_t)n0 * 256)
                                 : (Wkv + (size_t)(n0 - 256) * 256);

    const int tid = threadIdx.x;
    const int tmg = tid >> 4;
    const int tng = tid & 15;

    const int la_c  = tid >> 5;
    const int la_m4 = (tid & 31) << 2;
    const int lb_o  = tid >> 1;
    const int lb_k8 = (tid & 1) << 3;

    ull acc[8][4];
    #pragma unroll
    for (int i = 0; i < 8; ++i)
        #pragma unroll
        for (int j = 0; j < 4; ++j) acc[i][j] = 0ull;

    for (int kc = 0; kc < 256; kc += 16) {
        #pragma unroll
        for (int i = 0; i < 2; ++i) {
            int c = la_c + i * 8;
            float4 v = *(const float4*)(xb + (size_t)(kc + c) * NPIX + la_m4);
            *(float4*)(As + c * 128 + la_m4) = v;
        }
        #pragma unroll
        for (int i = 0; i < 2; ++i) {
            float4 wv = *(const float4*)(Wb + (size_t)lb_o * 256 + kc + lb_k8 + i * 4);
            Bs[(lb_k8 + i * 4 + 0) * 132 + lb_o] = wv.x;
            Bs[(lb_k8 + i * 4 + 1) * 132 + lb_o] = wv.y;
            Bs[(lb_k8 + i * 4 + 2) * 132 + lb_o] = wv.z;
            Bs[(lb_k8 + i * 4 + 3) * 132 + lb_o] = wv.w;
        }
        __syncthreads();

        #pragma unroll
        for (int kk = 0; kk < 16; ++kk) {
            float4 a0 = *(const float4*)(As + kk * 128 + tmg * 8);
            float4 a1 = *(const float4*)(As + kk * 128 + tmg * 8 + 4);
            float4 b0 = *(const float4*)(Bs + kk * 132 + tng * 8);
            float4 b1 = *(const float4*)(Bs + kk * 132 + tng * 8 + 4);
            ull bp0 = pk2(b0.x, b0.y), bp1 = pk2(b0.z, b0.w);
            ull bp2 = pk2(b1.x, b1.y), bp3 = pk2(b1.z, b1.w);
            float av[8] = {a0.x, a0.y, a0.z, a0.w, a1.x, a1.y, a1.z, a1.w};
            #pragma unroll
            for (int i = 0; i < 8; ++i) {
                ull ad = pk2(av[i], av[i]);
                acc[i][0] = fma2(ad, bp0, acc[i][0]);
                acc[i][1] = fma2(ad, bp1, acc[i][1]);
                acc[i][2] = fma2(ad, bp2, acc[i][2]);
                acc[i][3] = fma2(ad, bp3, acc[i][3]);
            }
        }
        __syncthreads();
    }

    const size_t mbase = (size_t)b * NPIX + pix0;
    #pragma unroll
    for (int i = 0; i < 8; ++i) {
        int m = tmg * 8 + i;
        float2 p0 = upk2(acc[i][0]), p1 = upk2(acc[i][1]);
        float2 p2 = upk2(acc[i][2]), p3 = upk2(acc[i][3]);
        float* op = g_qkv + (mbase + m) * QKVW + n0 + tng * 8;
        *(float4*)(op)     = make_float4(p0.x, p0.y, p1.x, p1.y);
        *(float4*)(op + 4) = make_float4(p2.x, p2.y, p3.x, p3.y);
    }
}

// =====================================================================
// Kernel 2: halo block attention, f32x2-packed
//   grid (64 blocks, 8 heads, 16 batch); 256 threads (8 warps).
//   QK: rows-packed f32x2 accumulators (query-row pairs), Q transposed
//       in smem so q pairs are single broadcast LDS.64.
//   PV: k-parity packed accumulators; P float4 halves are free reg pairs.
//   Softmax keeps P unnormalized; 1/sum applied in the PV epilogue.
// =====================================================================
#define QT_STRIDE 66      // Qt [32 d][64 rows] padded
#define KV_STRIDE 225     // K/V [32 d][196 k] padded (225 ≡ 1 mod 32)
#define OS_STRIDE 33      // output staging [64 rows][32 d] padded
#define AT_SMEM_FLOATS (32 * QT_STRIDE + 32 * KV_STRIDE + 64 * WIN2)
#define AT_SMEM_BYTES  (AT_SMEM_FLOATS * 4)   // 87,424

__global__ __launch_bounds__(256) void attn_kernel(const float* __restrict__ pos_bias,
                                                   float* __restrict__ out) {
    extern __shared__ float sm[];
    float* Qt = sm;                            // [32][66] = 2112 (reused as Os [64][33])
    float* KV = sm + 32 * QT_STRIDE;           // [32][225] = 7200 (K, then V)
    float* Ps = KV + 32 * KV_STRIDE;           // [64][196] = 12544

    const int nb = blockIdx.x, h = blockIdx.y, b = blockIdx.z;
    const int by = nb >> 3, bx = nb & 7;
    const int tid = threadIdx.x;
    const int w = tid >> 5, lane = tid & 31;
    const int w8 = w * 8;
    const float* qkv_b = g_qkv + (size_t)b * NPIX * QKVW;

    // ---- Q load -> Qt[d][row] (transposed) ----
    #pragma unroll
    for (int it = 0; it < 2; ++it) {
        int idx = tid + it * 256;               // 512 quads = 64 px * 8
        int r = idx >> 3, d4 = (idx & 7) << 2;
        int py = by * BSZ + (r >> 3), px = bx * BSZ + (r & 7);
        float4 q = *(const float4*)(qkv_b + (py * 64 + px) * QKVW + h * DHQK + d4);
        Qt[(d4 + 0) * QT_STRIDE + r] = q.x;
        Qt[(d4 + 1) * QT_STRIDE + r] = q.y;
        Qt[(d4 + 2) * QT_STRIDE + r] = q.z;
        Qt[(d4 + 3) * QT_STRIDE + r] = q.w;
    }
    // ---- K gather -> KV[d][k], zero-padded halo, float4 over d ----
    for (int idx = tid; idx < WIN2 * 8; idx += 256) {
        int kk = idx >> 3, d4 = (idx & 7) << 2;
        int wy = kk / WIN, wx = kk - wy * WIN;
        int py = by * BSZ - HALO + wy, px = bx * BSZ - HALO + wx;
        float4 v = make_float4(0.f, 0.f, 0.f, 0.f);
        if ((unsigned)py < 64u && (unsigned)px < 64u)
            v = *(const float4*)(qkv_b + (py * 64 + px) * QKVW + 256 + h * 64 + d4);
        KV[(d4 + 0) * KV_STRIDE + kk] = v.x;
        KV[(d4 + 1) * KV_STRIDE + kk] = v.y;
        KV[(d4 + 2) * KV_STRIDE + kk] = v.z;
        KV[(d4 + 3) * KV_STRIDE + kk] = v.w;
    }
    __syncthreads();

    // ---- QK scores: rows-packed pairs s2[j][nc] = (row 2j, row 2j+1) ----
    ull s2[4][7];
    #pragma unroll
    for (int j = 0; j < 4; ++j)
        #pragma unroll
        for (int nc = 0; nc < 7; ++nc) s2[j][nc] = 0ull;

    #pragma unroll 2
    for (int d = 0; d < 32; ++d) {
        ull kv2[7];
        #pragma unroll
        for (int nc = 0; nc < 7; ++nc) {
            float kf = KV[d * KV_STRIDE + nc * 32 + lane];
            kv2[nc] = pk2(kf, kf);
        }
        #pragma unroll
        for (int j = 0; j < 4; ++j) {
            ull q2 = *(const ull*)(Qt + d * QT_STRIDE + w8 + 2 * j);  // broadcast
            #pragma unroll
            for (int nc = 0; nc < 7; ++nc)
                s2[j][nc] = fma2(q2, kv2[nc], s2[j][nc]);
        }
    }

    // ---- bias + mask + softmax (unnormalized P to smem, inv kept in regs) ----
    const float* pbase = pos_bias + (size_t)(h * 64 + w8) * WIN2;
    const float NEG = -1e30f;
    float inv_[8];
    #pragma unroll
    for (int j = 0; j < 4; ++j) {
        #pragma unroll
        for (int rr = 0; rr < 2; ++rr) {
            const int mi = 2 * j + rr;
            float s[7];
            #pragma unroll
            for (int nc = 0; nc < 7; ++nc) {
                float2 t = upk2(s2[j][nc]);
                float sv = rr ? t.y : t.x;
                int kk = nc * 32 + lane;
                s[nc] = (kk < WIN2) ? fmaf(sv, SCALE_QK, pbase[mi * WIN2 + kk]) : NEG;
            }
            float mx = s[0];
            #pragma unroll
            for (int nc = 1; nc < 7; ++nc) mx = fmaxf(mx, s[nc]);
            #pragma unroll
            for (int off = 16; off > 0; off >>= 1)
                mx = fmaxf(mx, __shfl_xor_sync(0xffffffffu, mx, off));
            float sum = 0.f;
            #pragma unroll
            for (int nc = 0; nc < 7; ++nc) {
                float e = __expf(s[nc] - mx);
                s[nc] = e;
                sum += e;
            }
            #pragma unroll
            for (int off = 16; off > 0; off >>= 1)
                sum += __shfl_xor_sync(0xffffffffu, sum, off);
            inv_[mi] = 1.f / sum;
            float* prow = Ps + (w8 + mi) * WIN2;
            #pragma unroll
            for (int nc = 0; nc < 6; ++nc)
                prow[nc * 32 + lane] = s[nc];
            if (192 + lane < WIN2) prow[192 + lane] = s[6];
        }
    }
    __syncthreads();   // all warps done reading K

    // ---- V gather into the same buffer ----
    for (int idx = tid; idx < WIN2 * 8; idx += 256) {
        int kk = idx >> 3, d4 = (idx & 7) << 2;
        int wy = kk / WIN, wx = kk - wy * WIN;
        int py = by * BSZ - HALO + wy, px = bx * BSZ - HALO + wx;
        float4 v = make_float4(0.f, 0.f, 0.f, 0.f);
        if ((unsigned)py < 64u && (unsigned)px < 64u)
            v = *(const float4*)(qkv_b + (py * 64 + px) * QKVW + 256 + h * 64 + 32 + d4);
        KV[(d4 + 0) * KV_STRIDE + kk] = v.x;
        KV[(d4 + 1) * KV_STRIDE + kk] = v.y;
        KV[(d4 + 2) * KV_STRIDE + kk] = v.z;
        KV[(d4 + 3) * KV_STRIDE + kk] = v.w;
    }
    __syncthreads();

    // ---- PV: k-parity packed accumulators; lane == output dim d ----
    ull acc2[8];
    #pragma unroll
    for (int mi = 0; mi < 8; ++mi) acc2[mi] = 0ull;
    const float* vrow = KV + lane * KV_STRIDE;
    const float* prow = Ps + w8 * WIN2;
    for (int k4 = 0; k4 < WIN2 / 4; ++k4) {
        float v0 = vrow[k4 * 4 + 0];
        float v1 = vrow[k4 * 4 + 1];
        float v2 = vrow[k4 * 4 + 2];
        float v3 = vrow[k4 * 4 + 3];
        ull va = pk2(v0, v1), vb = pk2(v2, v3);
        #pragma unroll
        for (int mi = 0; mi < 8; ++mi) {
            float4 p = *(const float4*)(prow + mi * WIN2 + k4 * 4);   // broadcast
            acc2[mi] = fma2(pk2(p.x, p.y), va, acc2[mi]);
            acc2[mi] = fma2(pk2(p.z, p.w), vb, acc2[mi]);
        }
    }

    // ---- stage output (Os reuses Qt region, stride 33: conflict-free) ----
    float* Os = Qt;
    #pragma unroll
    for (int mi = 0; mi < 8; ++mi) {
        float2 t = upk2(acc2[mi]);
        Os[(w8 + mi) * OS_STRIDE + lane] = (t.x + t.y) * inv_[mi];
    }
    __syncthreads();

    const int d = tid >> 3, qy = tid & 7;
    float v0 = Os[(qy * 8 + 0) * OS_STRIDE + d], v1 = Os[(qy * 8 + 1) * OS_STRIDE + d];
    float v2 = Os[(qy * 8 + 2) * OS_STRIDE + d], v3 = Os[(qy * 8 + 3) * OS_STRIDE + d];
    float v4 = Os[(qy * 8 + 4) * OS_STRIDE + d], v5 = Os[(qy * 8 + 5) * OS_STRIDE + d];
    float v6 = Os[(qy * 8 + 6) * OS_STRIDE + d], v7 = Os[(qy * 8 + 7) * OS_STRIDE + d];
    float* op = out + ((size_t)((b * HEADS + h) * DHV + d) * 64 + by * BSZ + qy) * 64
                    + bx * BSZ;
    *(float4*)(op)     = make_float4(v0, v1, v2, v3);
    *(float4*)(op + 4) = make_float4(v4, v5, v6, v7);
}

// =====================================================================
extern "C" void kernel_launch(void* const* d_in, const int* in_sizes, int n_in,
                              void* d_out, int out_size) {
    const float* x   = (const float*)d_in[0];
    const float* Wq  = (const float*)d_in[1];
    const float* Wkv = (const float*)d_in[2];
    const float* pb  = (const float*)d_in[3];
    float* out = (float*)d_out;

    // 1) fused QKV projection (f32x2 SIMT — proven 575us)
    qkv_gemm<<<dim3(6, 512), 256>>>(x, Wq, Wkv);

    // 2) halo attention (f32x2-packed rewrite)
    cudaFuncSetAttribute(attn_kernel,
                         cudaFuncAttributeMaxDynamicSharedMemorySize, AT_SMEM_BYTES);
    attn_kernel<<<dim3(64, HEADS, NBATCH), 256, AT_SMEM_BYTES>>>(pb, out);
}

// round 5
// speedup vs baseline: 1.2986x; 1.0918x over previous
#include <cuda_runtime.h>
#include <cstdint>
#include <math.h>

typedef unsigned long long ull;

#define HEADS   8
#define DHQK    32
#define DHV     32
#define BSZ     8
#define HALO    3
#define WIN     14
#define WIN2    196
#define QKVW    768
#define NPIX    4096
#define NBATCH  16
#define SCALE_QK 0.17677669529663687f

// Scratch: fused qkv per pixel, layout [b][pix][768]:
//   [0,256)   q  : channel = head*32 + d
//   [256,768) kv : channel = head*64 + d (k: d<32, v: d>=32)
__device__ float g_qkv[(size_t)NBATCH * NPIX * QKVW];

// ---------- packed f32x2 helpers ----------
__device__ __forceinline__ ull pk2(float lo, float hi) {
    ull r; asm("mov.b64 %0, {%1, %2};" : "=l"(r) : "f"(lo), "f"(hi)); return r;
}
__device__ __forceinline__ ull fma2(ull a, ull b, ull c) {
    ull d; asm("fma.rn.f32x2 %0, %1, %2, %3;" : "=l"(d) : "l"(a), "l"(b), "l"(c)); return d;
}
__device__ __forceinline__ float2 upk2(ull v) {
    float2 r; asm("mov.b64 {%0, %1}, %2;" : "=f"(r.x), "=f"(r.y) : "l"(v)); return r;
}

// =====================================================================
// Kernel 1: fused QKV projection GEMM (f32x2), double-buffered,
//   conflict-free B fragments (thread n-tile 4+4).
// =====================================================================
__global__ __launch_bounds__(256) void qkv_gemm(const float* __restrict__ x,
                                                const float* __restrict__ Wq,
                                                const float* __restrict__ Wkv) {
    __shared__ float As[2][16 * 128];   // [buf][kk][m]
    __shared__ float Bs[2][16 * 132];   // [buf][kk][n] stride 132

    const int n0   = blockIdx.x * 128;
    const int mblk = blockIdx.y;
    const int b    = mblk >> 5;
    const int pix0 = (mblk & 31) << 7;

    const float* xb = x + ((size_t)b * 256) * NPIX + pix0;
    const float* Wb = (n0 < 256) ? (Wq + (size_t)n0 * 256)
                                 : (Wkv + (size_t)(n0 - 256) * 256);

    const int tid = threadIdx.x;
    const int tmg = tid >> 4;        // m group: rows tmg*8..+7
    const int tng = tid & 15;        // n group: cols tng*4..+3 and 64+tng*4..+3

    const int la_c  = tid >> 5;
    const int la_m4 = (tid & 31) << 2;
    const int lb_o  = tid >> 1;
    const int lb_k8 = (tid & 1) << 3;

    ull acc[8][4];
    #pragma unroll
    for (int i = 0; i < 8; ++i)
        #pragma unroll
        for (int j = 0; j < 4; ++j) acc[i][j] = 0ull;

    // ---- prologue: stage chunk 0 into buffer 0 ----
    #pragma unroll
    for (int i = 0; i < 2; ++i) {
        int c = la_c + i * 8;
        *(float4*)(&As[0][c * 128 + la_m4]) =
            *(const float4*)(xb + (size_t)c * NPIX + la_m4);
    }
    #pragma unroll
    for (int i = 0; i < 2; ++i) {
        float4 wv = *(const float4*)(Wb + (size_t)lb_o * 256 + lb_k8 + i * 4);
        Bs[0][(lb_k8 + i * 4 + 0) * 132 + lb_o] = wv.x;
        Bs[0][(lb_k8 + i * 4 + 1) * 132 + lb_o] = wv.y;
        Bs[0][(lb_k8 + i * 4 + 2) * 132 + lb_o] = wv.z;
        Bs[0][(lb_k8 + i * 4 + 3) * 132 + lb_o] = wv.w;
    }
    __syncthreads();

    for (int c = 0; c < 16; ++c) {
        const int cur = c & 1, nxt = cur ^ 1;

        // issue global loads for chunk c+1
        float4 a_reg[2], b_reg[2];
        if (c < 15) {
            const int kc = (c + 1) * 16;
            #pragma unroll
            for (int i = 0; i < 2; ++i)
                a_reg[i] = *(const float4*)(xb + (size_t)(kc + la_c + i * 8) * NPIX + la_m4);
            #pragma unroll
            for (int i = 0; i < 2; ++i)
                b_reg[i] = *(const float4*)(Wb + (size_t)lb_o * 256 + kc + lb_k8 + i * 4);
        }

        // compute chunk c
        #pragma unroll
        for (int kk = 0; kk < 16; ++kk) {
            float4 a0 = *(const float4*)(&As[cur][kk * 128 + tmg * 8]);
            float4 a1 = *(const float4*)(&As[cur][kk * 128 + tmg * 8 + 4]);
            float4 b0 = *(const float4*)(&Bs[cur][kk * 132 + tng * 4]);
            float4 b1 = *(const float4*)(&Bs[cur][kk * 132 + 64 + tng * 4]);
            ull bp0 = pk2(b0.x, b0.y), bp1 = pk2(b0.z, b0.w);
            ull bp2 = pk2(b1.x, b1.y), bp3 = pk2(b1.z, b1.w);
            float av[8] = {a0.x, a0.y, a0.z, a0.w, a1.x, a1.y, a1.z, a1.w};
            #pragma unroll
            for (int i = 0; i < 8; ++i) {
                ull ad = pk2(av[i], av[i]);
                acc[i][0] = fma2(ad, bp0, acc[i][0]);
                acc[i][1] = fma2(ad, bp1, acc[i][1]);
                acc[i][2] = fma2(ad, bp2, acc[i][2]);
                acc[i][3] = fma2(ad, bp3, acc[i][3]);
            }
        }

        // stage chunk c+1 into buffer nxt
        if (c < 15) {
            #pragma unroll
            for (int i = 0; i < 2; ++i)
                *(float4*)(&As[nxt][(la_c + i * 8) * 128 + la_m4]) = a_reg[i];
            #pragma unroll
            for (int i = 0; i < 2; ++i) {
                Bs[nxt][(lb_k8 + i * 4 + 0) * 132 + lb_o] = b_reg[i].x;
                Bs[nxt][(lb_k8 + i * 4 + 1) * 132 + lb_o] = b_reg[i].y;
                Bs[nxt][(lb_k8 + i * 4 + 2) * 132 + lb_o] = b_reg[i].z;
                Bs[nxt][(lb_k8 + i * 4 + 3) * 132 + lb_o] = b_reg[i].w;
            }
        }
        __syncthreads();
    }

    // ---- epilogue ----
    const size_t mbase = (size_t)b * NPIX + pix0;
    #pragma unroll
    for (int i = 0; i < 8; ++i) {
        int m = tmg * 8 + i;
        float2 p0 = upk2(acc[i][0]), p1 = upk2(acc[i][1]);
        float2 p2 = upk2(acc[i][2]), p3 = upk2(acc[i][3]);
        float* op = g_qkv + (mbase + m) * QKVW + n0 + tng * 4;
        *(float4*)(op)      = make_float4(p0.x, p0.y, p1.x, p1.y);
        *(float4*)(op + 64) = make_float4(p2.x, p2.y, p3.x, p3.y);
    }
}

// =====================================================================
// Kernel 2: halo block attention — single-sync, wide-LDS version.
//   Layouts: Qt [32 d][68] (broadcast LDS.128 pairs),
//            Kt [32 d][196] (lane-consecutive scalar reads),
//            Vs [32 d][196] (per-lane LDS.128 row reads),
//            Ps [64 row][196] fp32 (broadcast LDS.128).
//   One __syncthreads after gather; warps fully independent after.
//   Epilogue: lane d holds 8 consecutive x outputs -> 2 direct STG.128.
// =====================================================================
#define QT_ST 68
#define KV_ST 196
#define AT_SMEM_FLOATS (32 * QT_ST + 32 * KV_ST + 32 * KV_ST + 64 * WIN2)
#define AT_SMEM_BYTES  (AT_SMEM_FLOATS * 4)   // 109,056

__global__ __launch_bounds__(256) void attn_kernel(const float* __restrict__ pos_bias,
                                                   float* __restrict__ out) {
    extern __shared__ float sm[];
    float* Qt = sm;                        // 2176 f
    float* Kt = sm + 32 * QT_ST;           // 6272 f
    float* Vs = Kt + 32 * KV_ST;           // 6272 f
    float* Ps = Vs + 32 * KV_ST;           // 12544 f

    const int nb = blockIdx.x, h = blockIdx.y, b = blockIdx.z;
    const int by = nb >> 3, bx = nb & 7;
    const int tid = threadIdx.x;
    const int w = tid >> 5, lane = tid & 31;
    const int w8 = w * 8;
    const float* qkv_b = g_qkv + (size_t)b * NPIX * QKVW;

    // ---- gather phase (single) ----
    if (tid < WIN2) {     // K + V, pixel per thread (STS lane-consecutive)
        const int wy = tid / WIN, wx = tid - wy * WIN;
        const int py = by * BSZ - HALO + wy, px = bx * BSZ - HALO + wx;
        const bool ok = ((unsigned)py < 64u) && ((unsigned)px < 64u);
        const float* src = qkv_b + (py * 64 + px) * QKVW + 256 + h * 64;
        const float4 z4 = make_float4(0.f, 0.f, 0.f, 0.f);
        #pragma unroll
        for (int i = 0; i < 8; ++i) {
            float4 kv = ok ? *(const float4*)(src + 4 * i) : z4;
            Kt[(4 * i + 0) * KV_ST + tid] = kv.x;
            Kt[(4 * i + 1) * KV_ST + tid] = kv.y;
            Kt[(4 * i + 2) * KV_ST + tid] = kv.z;
            Kt[(4 * i + 3) * KV_ST + tid] = kv.w;
        }
        #pragma unroll
        for (int i = 0; i < 8; ++i) {
            float4 vv = ok ? *(const float4*)(src + 32 + 4 * i) : z4;
            Vs[(4 * i + 0) * KV_ST + tid] = vv.x;
            Vs[(4 * i + 1) * KV_ST + tid] = vv.y;
            Vs[(4 * i + 2) * KV_ST + tid] = vv.z;
            Vs[(4 * i + 3) * KV_ST + tid] = vv.w;
        }
    }
    if (tid >= 192) {     // Q, pixel per thread
        const int r = tid - 192;
        const int py = by * BSZ + (r >> 3), px = bx * BSZ + (r & 7);
        const float* src = qkv_b + (py * 64 + px) * QKVW + h * DHQK;
        #pragma unroll
        for (int i = 0; i < 8; ++i) {
            float4 q = *(const float4*)(src + 4 * i);
            Qt[(4 * i + 0) * QT_ST + r] = q.x;
            Qt[(4 * i + 1) * QT_ST + r] = q.y;
            Qt[(4 * i + 2) * QT_ST + r] = q.z;
            Qt[(4 * i + 3) * QT_ST + r] = q.w;
        }
    }
    __syncthreads();      // the only barrier

    // ---- QK: rows-packed f32x2, 2 broadcast LDS.128 per d for Q ----
    ull s2[4][7];
    #pragma unroll
    for (int j = 0; j < 4; ++j)
        #pragma unroll
        for (int nc = 0; nc < 7; ++nc) s2[j][nc] = 0ull;

    #pragma unroll 2
    for (int d = 0; d < 32; ++d) {
        ull kv2[7];
        #pragma unroll
        for (int nc = 0; nc < 7; ++nc) {
            float kf = Kt[d * KV_ST + nc * 32 + lane];
            kv2[nc] = pk2(kf, kf);
        }
        float4 qa = *(const float4*)(Qt + d * QT_ST + w8);       // rows 0-3 (bcast)
        float4 qb = *(const float4*)(Qt + d * QT_ST + w8 + 4);   // rows 4-7
        ull q01 = pk2(qa.x, qa.y), q23 = pk2(qa.z, qa.w);
        ull q45 = pk2(qb.x, qb.y), q67 = pk2(qb.z, qb.w);
        #pragma unroll
        for (int nc = 0; nc < 7; ++nc) {
            s2[0][nc] = fma2(q01, kv2[nc], s2[0][nc]);
            s2[1][nc] = fma2(q23, kv2[nc], s2[1][nc]);
            s2[2][nc] = fma2(q45, kv2[nc], s2[2][nc]);
            s2[3][nc] = fma2(q67, kv2[nc], s2[3][nc]);
        }
    }

    // ---- bias + mask + softmax (unnormalized P; inv kept in regs) ----
    const float* pbase = pos_bias + (size_t)(h * 64 + w8) * WIN2;
    const float NEG = -1e30f;
    float inv_[8];
    #pragma unroll
    for (int j = 0; j < 4; ++j) {
        #pragma unroll
        for (int rr = 0; rr < 2; ++rr) {
            const int mi = 2 * j + rr;
            float s[7];
            #pragma unroll
            for (int nc = 0; nc < 7; ++nc) {
                float2 t = upk2(s2[j][nc]);
                float sv = rr ? t.y : t.x;
                int kk = nc * 32 + lane;
                s[nc] = (kk < WIN2) ? fmaf(sv, SCALE_QK, pbase[mi * WIN2 + kk]) : NEG;
            }
            float mx = s[0];
            #pragma unroll
            for (int nc = 1; nc < 7; ++nc) mx = fmaxf(mx, s[nc]);
            #pragma unroll
            for (int off = 16; off > 0; off >>= 1)
                mx = fmaxf(mx, __shfl_xor_sync(0xffffffffu, mx, off));
            float sum = 0.f;
            #pragma unroll
            for (int nc = 0; nc < 7; ++nc) {
                float e = __expf(s[nc] - mx);
                s[nc] = e;
                sum += e;
            }
            #pragma unroll
            for (int off = 16; off > 0; off >>= 1)
                sum += __shfl_xor_sync(0xffffffffu, sum, off);
            inv_[mi] = 1.f / sum;
            float* prow = Ps + (w8 + mi) * WIN2;
            #pragma unroll
            for (int nc = 0; nc < 6; ++nc)
                prow[nc * 32 + lane] = s[nc];
            if (lane < 4) prow[192 + lane] = s[6];
        }
    }
    // no barrier: PV reads only this warp's P rows + Vs from the gather phase

    // ---- PV: V via LDS.128, P via broadcast LDS.128, k-parity f32x2 ----
    ull acc2[8];
    #pragma unroll
    for (int mi = 0; mi < 8; ++mi) acc2[mi] = 0ull;
    const float* vrow = Vs + lane * KV_ST;
    const float* prow = Ps + w8 * WIN2;
    for (int k4 = 0; k4 < WIN2 / 4; ++k4) {
        float4 v = *(const float4*)(vrow + 4 * k4);
        ull va = pk2(v.x, v.y), vb = pk2(v.z, v.w);
        #pragma unroll
        for (int mi = 0; mi < 8; ++mi) {
            float4 p = *(const float4*)(prow + mi * WIN2 + 4 * k4);
            acc2[mi] = fma2(pk2(p.x, p.y), va, acc2[mi]);
            acc2[mi] = fma2(pk2(p.z, p.w), vb, acc2[mi]);
        }
    }

    // ---- epilogue: lane d writes out[d][by*8+w][bx*8 .. +7] directly ----
    float o[8];
    #pragma unroll
    for (int mi = 0; mi < 8; ++mi) {
        float2 t = upk2(acc2[mi]);
        o[mi] = (t.x + t.y) * inv_[mi];
    }
    float* op = out + (((size_t)(b * HEADS + h) * DHV + lane) * 64 + by * BSZ + w) * 64
                    + bx * BSZ;
    *(float4*)(op)     = make_float4(o[0], o[1], o[2], o[3]);
    *(float4*)(op + 4) = make_float4(o[4], o[5], o[6], o[7]);
}

// =====================================================================
extern "C" void kernel_launch(void* const* d_in, const int* in_sizes, int n_in,
                              void* d_out, int out_size) {
    const float* x   = (const float*)d_in[0];
    const float* Wq  = (const float*)d_in[1];
    const float* Wkv = (const float*)d_in[2];
    const float* pb  = (const float*)d_in[3];
    float* out = (float*)d_out;

    // 1) fused QKV projection (f32x2, double-buffered, conflict-free B)
    qkv_gemm<<<dim3(6, 512), 256>>>(x, Wq, Wkv);

    // 2) halo attention (single-sync, wide-LDS)
    cudaFuncSetAttribute(attn_kernel,
                         cudaFuncAttributeMaxDynamicSharedMemorySize, AT_SMEM_BYTES);
    attn_kernel<<<dim3(64, HEADS, NBATCH), 256, AT_SMEM_BYTES>>>(pb, out);
}

// round 6
// speedup vs baseline: 1.5557x; 1.1980x over previous
#include <cuda_runtime.h>
#include <cstdint>
#include <math.h>

typedef unsigned long long ull;

#define HEADS   8
#define DHQK    32
#define DHV     32
#define BSZ     8
#define HALO    3
#define WIN     14
#define WIN2    196
#define QKVW    768
#define NPIX    4096
#define NBATCH  16
#define SCALE_QK 0.17677669529663687f

// Scratch: fused qkv per pixel, layout [b][pix][768]:
//   [0,256)   q  : channel = head*32 + d
//   [256,768) kv : channel = head*64 + d (k: d<32, v: d>=32)
__device__ float g_qkv[(size_t)NBATCH * NPIX * QKVW];

// ---------- packed f32x2 helpers ----------
__device__ __forceinline__ ull pk2(float lo, float hi) {
    ull r; asm("mov.b64 %0, {%1, %2};" : "=l"(r) : "f"(lo), "f"(hi)); return r;
}
__device__ __forceinline__ ull fma2(ull a, ull b, ull c) {
    ull d; asm("fma.rn.f32x2 %0, %1, %2, %3;" : "=l"(d) : "l"(a), "l"(b), "l"(c)); return d;
}
__device__ __forceinline__ float2 upk2(ull v) {
    float2 r; asm("mov.b64 {%0, %1}, %2;" : "=f"(r.x), "=f"(r.y) : "l"(v)); return r;
}

// =====================================================================
// Kernel 1: fused QKV projection GEMM (f32x2), double-buffered,
//   conflict-free B fragments (thread n-tile 4+4).  [R5: ~435us]
// =====================================================================
__global__ __launch_bounds__(256) void qkv_gemm(const float* __restrict__ x,
                                                const float* __restrict__ Wq,
                                                const float* __restrict__ Wkv) {
    __shared__ float As[2][16 * 128];   // [buf][kk][m]
    __shared__ float Bs[2][16 * 132];   // [buf][kk][n] stride 132

    const int n0   = blockIdx.x * 128;
    const int mblk = blockIdx.y;
    const int b    = mblk >> 5;
    const int pix0 = (mblk & 31) << 7;

    const float* xb = x + ((size_t)b * 256) * NPIX + pix0;
    const float* Wb = (n0 < 256) ? (Wq + (size_t)n0 * 256)
                                 : (Wkv + (size_t)(n0 - 256) * 256);

    const int tid = threadIdx.x;
    const int tmg = tid >> 4;
    const int tng = tid & 15;

    const int la_c  = tid >> 5;
    const int la_m4 = (tid & 31) << 2;
    const int lb_o  = tid >> 1;
    const int lb_k8 = (tid & 1) << 3;

    ull acc[8][4];
    #pragma unroll
    for (int i = 0; i < 8; ++i)
        #pragma unroll
        for (int j = 0; j < 4; ++j) acc[i][j] = 0ull;

    #pragma unroll
    for (int i = 0; i < 2; ++i) {
        int c = la_c + i * 8;
        *(float4*)(&As[0][c * 128 + la_m4]) =
            *(const float4*)(xb + (size_t)c * NPIX + la_m4);
    }
    #pragma unroll
    for (int i = 0; i < 2; ++i) {
        float4 wv = *(const float4*)(Wb + (size_t)lb_o * 256 + lb_k8 + i * 4);
        Bs[0][(lb_k8 + i * 4 + 0) * 132 + lb_o] = wv.x;
        Bs[0][(lb_k8 + i * 4 + 1) * 132 + lb_o] = wv.y;
        Bs[0][(lb_k8 + i * 4 + 2) * 132 + lb_o] = wv.z;
        Bs[0][(lb_k8 + i * 4 + 3) * 132 + lb_o] = wv.w;
    }
    __syncthreads();

    for (int c = 0; c < 16; ++c) {
        const int cur = c & 1, nxt = cur ^ 1;

        float4 a_reg[2], b_reg[2];
        if (c < 15) {
            const int kc = (c + 1) * 16;
            #pragma unroll
            for (int i = 0; i < 2; ++i)
                a_reg[i] = *(const float4*)(xb + (size_t)(kc + la_c + i * 8) * NPIX + la_m4);
            #pragma unroll
            for (int i = 0; i < 2; ++i)
                b_reg[i] = *(const float4*)(Wb + (size_t)lb_o * 256 + kc + lb_k8 + i * 4);
        }

        #pragma unroll
        for (int kk = 0; kk < 16; ++kk) {
            float4 a0 = *(const float4*)(&As[cur][kk * 128 + tmg * 8]);
            float4 a1 = *(const float4*)(&As[cur][kk * 128 + tmg * 8 + 4]);
            float4 b0 = *(const float4*)(&Bs[cur][kk * 132 + tng * 4]);
            float4 b1 = *(const float4*)(&Bs[cur][kk * 132 + 64 + tng * 4]);
            ull bp0 = pk2(b0.x, b0.y), bp1 = pk2(b0.z, b0.w);
            ull bp2 = pk2(b1.x, b1.y), bp3 = pk2(b1.z, b1.w);
            float av[8] = {a0.x, a0.y, a0.z, a0.w, a1.x, a1.y, a1.z, a1.w};
            #pragma unroll
            for (int i = 0; i < 8; ++i) {
                ull ad = pk2(av[i], av[i]);
                acc[i][0] = fma2(ad, bp0, acc[i][0]);
                acc[i][1] = fma2(ad, bp1, acc[i][1]);
                acc[i][2] = fma2(ad, bp2, acc[i][2]);
                acc[i][3] = fma2(ad, bp3, acc[i][3]);
            }
        }

        if (c < 15) {
            #pragma unroll
            for (int i = 0; i < 2; ++i)
                *(float4*)(&As[nxt][(la_c + i * 8) * 128 + la_m4]) = a_reg[i];
            #pragma unroll
            for (int i = 0; i < 2; ++i) {
                Bs[nxt][(lb_k8 + i * 4 + 0) * 132 + lb_o] = b_reg[i].x;
                Bs[nxt][(lb_k8 + i * 4 + 1) * 132 + lb_o] = b_reg[i].y;
                Bs[nxt][(lb_k8 + i * 4 + 2) * 132 + lb_o] = b_reg[i].z;
                Bs[nxt][(lb_k8 + i * 4 + 3) * 132 + lb_o] = b_reg[i].w;
            }
        }
        __syncthreads();
    }

    const size_t mbase = (size_t)b * NPIX + pix0;
    #pragma unroll
    for (int i = 0; i < 8; ++i) {
        int m = tmg * 8 + i;
        float2 p0 = upk2(acc[i][0]), p1 = upk2(acc[i][1]);
        float2 p2 = upk2(acc[i][2]), p3 = upk2(acc[i][3]);
        float* op = g_qkv + (mbase + m) * QKVW + n0 + tng * 4;
        *(float4*)(op)      = make_float4(p0.x, p0.y, p1.x, p1.y);
        *(float4*)(op + 64) = make_float4(p2.x, p2.y, p3.x, p3.y);
    }
}

// =====================================================================
// Kernel 2: halo block attention — single-sync, balanced gather.
//   Qt [32 d][68]   : broadcast LDS.128 pairs in QK
//   Kt [32 d][197]  : stride≡5 mod 32 → conflict-free quad STS + 1-wf reads
//   Vs [196 k][36]  : k-major → single conflict-free STS.128 gather,
//                     conflict-free lane-consecutive reads in PV
//   Ps [64 r][196]  : broadcast LDS.128 in PV
//   One __syncthreads; direct STG.128 epilogue.
// =====================================================================
#define QT_ST 68
#define KT_ST 197
#define VS_ST 36
#define AT_SMEM_FLOATS (32 * QT_ST + 32 * KT_ST + WIN2 * VS_ST + 64 * WIN2)
#define AT_SMEM_BYTES  (AT_SMEM_FLOATS * 4)   // 112,320

__global__ __launch_bounds__(256, 2) void attn_kernel(const float* __restrict__ pos_bias,
                                                      float* __restrict__ out) {
    extern __shared__ float sm[];
    float* Qt = sm;                        // 2176 f
    float* Kt = sm + 32 * QT_ST;           // 6304 f
    float* Vs = Kt + 32 * KT_ST;           // 7056 f
    float* Ps = Vs + WIN2 * VS_ST;         // 12544 f

    const int nb = blockIdx.x, h = blockIdx.y, b = blockIdx.z;
    const int by = nb >> 3, bx = nb & 7;
    const int tid = threadIdx.x;
    const int w = tid >> 5, lane = tid & 31;
    const int w8 = w * 8;
    const float* qkv_b = g_qkv + (size_t)b * NPIX * QKVW;

    // ---- gather: K + V, 1568 (pixel, d-quad) items over all threads ----
    for (int idx = tid; idx < WIN2 * 8; idx += 256) {
        const int kk = idx >> 3, d4 = (idx & 7) << 2;
        const int wy = kk / WIN, wx = kk - wy * WIN;
        const int py = by * BSZ - HALO + wy, px = bx * BSZ - HALO + wx;
        const bool ok = ((unsigned)py < 64u) && ((unsigned)px < 64u);
        const float4 z4 = make_float4(0.f, 0.f, 0.f, 0.f);
        const float* src = qkv_b + (py * 64 + px) * QKVW + 256 + h * 64;
        float4 kv = ok ? *(const float4*)(src + d4) : z4;
        Kt[(d4 + 0) * KT_ST + kk] = kv.x;
        Kt[(d4 + 1) * KT_ST + kk] = kv.y;
        Kt[(d4 + 2) * KT_ST + kk] = kv.z;
        Kt[(d4 + 3) * KT_ST + kk] = kv.w;
        float4 vv = ok ? *(const float4*)(src + 32 + d4) : z4;
        *(float4*)(Vs + kk * VS_ST + d4) = vv;
    }
    // ---- gather: Q, 512 items (r = idx&63 so STS banks span rows) ----
    #pragma unroll
    for (int it = 0; it < 2; ++it) {
        const int idx = tid + it * 256;
        const int q4 = (idx >> 6) << 2, r = idx & 63;
        const int py = by * BSZ + (r >> 3), px = bx * BSZ + (r & 7);
        float4 qv = *(const float4*)(qkv_b + (py * 64 + px) * QKVW + h * DHQK + q4);
        Qt[(q4 + 0) * QT_ST + r] = qv.x;
        Qt[(q4 + 1) * QT_ST + r] = qv.y;
        Qt[(q4 + 2) * QT_ST + r] = qv.z;
        Qt[(q4 + 3) * QT_ST + r] = qv.w;
    }
    __syncthreads();      // the only barrier

    // ---- QK: rows-packed f32x2 ----
    ull s2[4][7];
    #pragma unroll
    for (int j = 0; j < 4; ++j)
        #pragma unroll
        for (int nc = 0; nc < 7; ++nc) s2[j][nc] = 0ull;

    #pragma unroll 4
    for (int d = 0; d < 32; ++d) {
        ull kv2[7];
        #pragma unroll
        for (int nc = 0; nc < 7; ++nc) {
            float kf = Kt[d * KT_ST + nc * 32 + lane];
            kv2[nc] = pk2(kf, kf);
        }
        float4 qa = *(const float4*)(Qt + d * QT_ST + w8);       // rows 0-3 (bcast)
        float4 qb = *(const float4*)(Qt + d * QT_ST + w8 + 4);   // rows 4-7
        ull q01 = pk2(qa.x, qa.y), q23 = pk2(qa.z, qa.w);
        ull q45 = pk2(qb.x, qb.y), q67 = pk2(qb.z, qb.w);
        #pragma unroll
        for (int nc = 0; nc < 7; ++nc) {
            s2[0][nc] = fma2(q01, kv2[nc], s2[0][nc]);
            s2[1][nc] = fma2(q23, kv2[nc], s2[1][nc]);
            s2[2][nc] = fma2(q45, kv2[nc], s2[2][nc]);
            s2[3][nc] = fma2(q67, kv2[nc], s2[3][nc]);
        }
    }

    // ---- bias + mask + softmax (unnormalized P; inv kept in regs) ----
    const float* pbase = pos_bias + (size_t)(h * 64 + w8) * WIN2;
    const float NEG = -1e30f;
    float inv_[8];
    #pragma unroll
    for (int j = 0; j < 4; ++j) {
        #pragma unroll
        for (int rr = 0; rr < 2; ++rr) {
            const int mi = 2 * j + rr;
            float s[7];
            #pragma unroll
            for (int nc = 0; nc < 7; ++nc) {
                float2 t = upk2(s2[j][nc]);
                float sv = rr ? t.y : t.x;
                int kk = nc * 32 + lane;
                s[nc] = (kk < WIN2) ? fmaf(sv, SCALE_QK, pbase[mi * WIN2 + kk]) : NEG;
            }
            float mx = s[0];
            #pragma unroll
            for (int nc = 1; nc < 7; ++nc) mx = fmaxf(mx, s[nc]);
            #pragma unroll
            for (int off = 16; off > 0; off >>= 1)
                mx = fmaxf(mx, __shfl_xor_sync(0xffffffffu, mx, off));
            float sum = 0.f;
            #pragma unroll
            for (int nc = 0; nc < 7; ++nc) {
                float e = __expf(s[nc] - mx);
                s[nc] = e;
                sum += e;
            }
            #pragma unroll
            for (int off = 16; off > 0; off >>= 1)
                sum += __shfl_xor_sync(0xffffffffu, sum, off);
            inv_[mi] = 1.f / sum;
            float* prow = Ps + (w8 + mi) * WIN2;
            #pragma unroll
            for (int nc = 0; nc < 6; ++nc)
                prow[nc * 32 + lane] = s[nc];
            if (lane < 4) prow[192 + lane] = s[6];
        }
    }
    // no barrier: PV reads only this warp's P rows + Vs from the gather phase

    // ---- PV: V k-major scalar reads (conflict-free), P broadcast LDS.128 ----
    ull acc2[8];
    #pragma unroll
    for (int mi = 0; mi < 8; ++mi) acc2[mi] = 0ull;
    const float* prow = Ps + w8 * WIN2;
    #pragma unroll 2
    for (int k4 = 0; k4 < WIN2 / 4; ++k4) {
        float v0 = Vs[(4 * k4 + 0) * VS_ST + lane];
        float v1 = Vs[(4 * k4 + 1) * VS_ST + lane];
        float v2 = Vs[(4 * k4 + 2) * VS_ST + lane];
        float v3 = Vs[(4 * k4 + 3) * VS_ST + lane];
        ull va = pk2(v0, v1), vb = pk2(v2, v3);
        #pragma unroll
        for (int mi = 0; mi < 8; ++mi) {
            float4 p = *(const float4*)(prow + mi * WIN2 + 4 * k4);
            acc2[mi] = fma2(pk2(p.x, p.y), va, acc2[mi]);
            acc2[mi] = fma2(pk2(p.z, p.w), vb, acc2[mi]);
        }
    }

    // ---- epilogue: lane d writes out[d][by*8+w][bx*8 .. +7] directly ----
    float o[8];
    #pragma unroll
    for (int mi = 0; mi < 8; ++mi) {
        float2 t = upk2(acc2[mi]);
        o[mi] = (t.x + t.y) * inv_[mi];
    }
    float* op = out + (((size_t)(b * HEADS + h) * DHV + lane) * 64 + by * BSZ + w) * 64
                    + bx * BSZ;
    *(float4*)(op)     = make_float4(o[0], o[1], o[2], o[3]);
    *(float4*)(op + 4) = make_float4(o[4], o[5], o[6], o[7]);
}

// =====================================================================
extern "C" void kernel_launch(void* const* d_in, const int* in_sizes, int n_in,
                              void* d_out, int out_size) {
    const float* x   = (const float*)d_in[0];
    const float* Wq  = (const float*)d_in[1];
    const float* Wkv = (const float*)d_in[2];
    const float* pb  = (const float*)d_in[3];
    float* out = (float*)d_out;

    // 1) fused QKV projection (f32x2, double-buffered, conflict-free B)
    qkv_gemm<<<dim3(6, 512), 256>>>(x, Wq, Wkv);

    // 2) halo attention (single-sync, balanced conflict-free gather)
    cudaFuncSetAttribute(attn_kernel,
                         cudaFuncAttributeMaxDynamicSharedMemorySize, AT_SMEM_BYTES);
    attn_kernel<<<dim3(64, HEADS, NBATCH), 256, AT_SMEM_BYTES>>>(pb, out);
}